// round 12
// baseline (speedup 1.0000x reference)
#include <cuda_runtime.h>
#include <cstdint>

#define HH   480
#define WW   864
#define W4   216                 // WW/4
#define HW4  (HH*W4)             // 103680 float4 per sample
#define HWX  (HH*WW)
#define MAXB 224
#define FROWS 8                  // rows filled per block
#define FBX  (HH/FROWS)          // 60 blocks per sample
#define NT   256

// Raw search results (single-owner writes, always overwritten before use).
__device__ int g_cnt [MAXB];
__device__ int g_minr[MAXB];
__device__ int g_maxr[MAXB];
__device__ int g_minc[MAXB];
__device__ int g_maxc[MAXB];
__device__ int g_ready[MAXB];    // arrivals (0..5), reset at exit
__device__ int g_flag [MAXB];    // all 5 results ready,  reset at exit
__device__ int g_exit = 0;       // last-block-out resets everything

__global__ __launch_bounds__(NT) void ram_fused(const float4* __restrict__ mask,
                                                const int* __restrict__ n_pts,
                                                const int* __restrict__ n_loose,
                                                float4* __restrict__ out,
                                                float* __restrict__ out_bbox,
                                                int B)
{
    const int t = threadIdx.x;
    const int x = blockIdx.x;          // 0..59 ; x<5 also runs a search task
    const int b = blockIdx.y;
    const float4* base = mask + (size_t)b * HW4;

    __shared__ int sh[8];
    __shared__ int s_val;

    // ================= producer: early-exit searches (blocks x<5) ==========
    if (x < 5) {
        int result = 0;
        if (x == 0) {
            // count with early-out at >= thr
            const int thr = *n_pts;
            int total = 0;
            for (int start = 0; start < HW4; start += NT) {
                const int idx = start + t;
                int c = 0;
                if (idx < HW4) {
                    float4 v = base[idx];
                    c = (v.x > 0.5f) + (v.y > 0.5f) + (v.z > 0.5f) + (v.w > 0.5f);
                }
                c = __reduce_add_sync(0xffffffffu, c);
                __syncthreads();
                if ((t & 31) == 0) sh[t >> 5] = c;
                __syncthreads();
                if (t == 0) {
                    int s = 0;
                    #pragma unroll
                    for (int i = 0; i < 8; i++) s += sh[i];
                    s_val = s;
                }
                __syncthreads();
                total += s_val;
                if (total >= thr) break;
            }
            result = total;
        } else if (x == 1) {
            // min_r: top-down row probe
            result = HH;
            for (int r = 0; r < HH; r++) {
                bool hit = false;
                if (t < W4) {
                    float4 v = base[(size_t)r * W4 + t];
                    hit = (fmaxf(fmaxf(v.x, v.y), fmaxf(v.z, v.w)) > 0.5f);
                }
                if (__syncthreads_or((int)hit)) { result = r; break; }
            }
        } else if (x == 2) {
            // max_r: bottom-up row probe
            result = -1;
            for (int r = HH - 1; r >= 0; r--) {
                bool hit = false;
                if (t < W4) {
                    float4 v = base[(size_t)r * W4 + t];
                    hit = (fmaxf(fmaxf(v.x, v.y), fmaxf(v.z, v.w)) > 0.5f);
                }
                if (__syncthreads_or((int)hit)) { result = r; break; }
            }
        } else if (x == 3) {
            // min_c: left-to-right float4-column probe
            result = WW;
            for (int cg = 0; cg < W4; cg++) {
                int lm = 1 << 30;
                for (int r = t; r < HH; r += NT) {
                    float4 v = base[(size_t)r * W4 + cg];
                    int cm = (v.x > 0.5f) ? 4*cg
                           : (v.y > 0.5f) ? 4*cg + 1
                           : (v.z > 0.5f) ? 4*cg + 2
                           : (v.w > 0.5f) ? 4*cg + 3 : (1 << 30);
                    lm = min(lm, cm);
                }
                lm = __reduce_min_sync(0xffffffffu, lm);
                __syncthreads();
                if ((t & 31) == 0) sh[t >> 5] = lm;
                __syncthreads();
                if (t == 0) {
                    int s = sh[0];
                    #pragma unroll
                    for (int i = 1; i < 8; i++) s = min(s, sh[i]);
                    s_val = s;
                }
                __syncthreads();
                if (s_val < (1 << 30)) { result = s_val; break; }
            }
        } else {
            // max_c: right-to-left float4-column probe
            result = -1;
            for (int cg = W4 - 1; cg >= 0; cg--) {
                int lm = -1;
                for (int r = t; r < HH; r += NT) {
                    float4 v = base[(size_t)r * W4 + cg];
                    int cm = (v.w > 0.5f) ? 4*cg + 3
                           : (v.z > 0.5f) ? 4*cg + 2
                           : (v.y > 0.5f) ? 4*cg + 1
                           : (v.x > 0.5f) ? 4*cg : -1;
                    lm = max(lm, cm);
                }
                lm = __reduce_max_sync(0xffffffffu, lm);
                __syncthreads();
                if ((t & 31) == 0) sh[t >> 5] = lm;
                __syncthreads();
                if (t == 0) {
                    int s = sh[0];
                    #pragma unroll
                    for (int i = 1; i < 8; i++) s = max(s, sh[i]);
                    s_val = s;
                }
                __syncthreads();
                if (s_val >= 0) { result = s_val; break; }
            }
        }

        if (t == 0) {
            if      (x == 0) g_cnt [b] = result;
            else if (x == 1) g_minr[b] = result;
            else if (x == 2) g_maxr[b] = result;
            else if (x == 3) g_minc[b] = result;
            else             g_maxc[b] = result;
            __threadfence();
            if (atomicAdd(&g_ready[b], 1) == 4)    // 5th arrival releases
                atomicExch(&g_flag[b], 1);
        }
    }

    // ================= consumer: fill 8 rows =================
    __shared__ int4 sbb;
    if (t == 0) {
        while (atomicAdd(&g_flag[b], 0) == 0) __nanosleep(32);
        __threadfence();   // acquire
        const int thr = *n_pts, loose = *n_loose;
        const bool full = g_cnt[b] < thr;
        int y0 = full ? 0      : max(0, min(HH - 1, g_minr[b] - loose));
        int y1 = full ? HH - 1 : max(0, min(HH - 1, g_maxr[b] + loose));
        int x0 = full ? 0      : max(0, min(WW - 1, g_minc[b] - loose));
        int x1 = full ? WW - 1 : max(0, min(WW - 1, g_maxc[b] + loose));
        sbb = make_int4(y0, y1, x0, x1);
        if (out_bbox && x == 0) {
            out_bbox[b * 4 + 0] = (float)y0;
            out_bbox[b * 4 + 1] = (float)y1;
            out_bbox[b * 4 + 2] = (float)x0;
            out_bbox[b * 4 + 3] = (float)x1;
        }
    }
    __syncthreads();

    if (t < W4) {
        const int4 bb = sbb;
        const int r0 = x * FROWS;
        const int c = t * 4;
        float4 vin;
        vin.x = (c     >= bb.z && c     <= bb.w) ? 1.f : 0.f;
        vin.y = (c + 1 >= bb.z && c + 1 <= bb.w) ? 1.f : 0.f;
        vin.z = (c + 2 >= bb.z && c + 2 <= bb.w) ? 1.f : 0.f;
        vin.w = (c + 3 >= bb.z && c + 3 <= bb.w) ? 1.f : 0.f;
        const float4 vz = make_float4(0.f, 0.f, 0.f, 0.f);

        float4* p = out + (size_t)b * HW4 + (size_t)r0 * W4 + t;
        #pragma unroll
        for (int j = 0; j < FROWS; j++) {
            const int r = r0 + j;
            p[(size_t)j * W4] = (r >= bb.x && r <= bb.y) ? vin : vz;
        }
    }

    // ================= reset (last block out) =================
    if (t == 0) {
        if (atomicAdd(&g_exit, 1) == (int)(gridDim.x * gridDim.y) - 1) {
            for (int i = 0; i < B; i++) { g_ready[i] = 0; g_flag[i] = 0; }
            __threadfence();
            g_exit = 0;
        }
    }
}

extern "C" void kernel_launch(void* const* d_in, const int* in_sizes, int n_in,
                              void* d_out, int out_size) {
    const float* mask = (const float*)d_in[0];
    const int* n_pts  = (const int*)d_in[1];
    const int* loose  = (const int*)d_in[2];
    float* out        = (float*)d_out;

    const int B = in_sizes[0] / HWX;
    const int att_elems = B * HWX;
    float* out_bbox = (out_size >= att_elems + 4 * B) ? (out + att_elems) : nullptr;

    ram_fused<<<dim3(FBX, B), NT>>>((const float4*)mask, n_pts, loose,
                                    (float4*)out, out_bbox, B);
}

// round 13
// speedup vs baseline: 1.6564x; 1.6564x over previous
#include <cuda_runtime.h>
#include <cstdint>

#define HH   480
#define WW   864
#define W4   216                 // WW/4
#define HW4  (HH*W4)             // 103680 float4 per sample
#define HWX  (HH*WW)
#define MAXB 224
#define FROWS 8                  // rows per fill block
#define FBX  (HH/FROWS)          // 60
#define NTA  256                 // bbox-search block size

// Raw search results, single-owner writes (always overwritten -> no reset).
__device__ int g_cnt [MAXB];
__device__ int g_minr[MAXB];
__device__ int g_maxr[MAXB];
__device__ int g_minc[MAXB];
__device__ int g_maxc[MAXB];

// ---------------------------------------------------------------------------
// Kernel A: grid (5, B). Each block runs ONE early-exit search task.
// ---------------------------------------------------------------------------
__global__ __launch_bounds__(NTA) void ram_bbox(const float4* __restrict__ mask,
                                                const int* __restrict__ n_pts)
{
    const int t    = threadIdx.x;
    const int task = blockIdx.x;
    const int b    = blockIdx.y;
    const float4* base = mask + (size_t)b * HW4;

    __shared__ int sh[8];
    __shared__ int s_val;

    if (task == 0) {
        // ---- count with early-out at >= thr ----
        const int thr = *n_pts;
        int total = 0;
        for (int start = 0; start < HW4; start += NTA) {
            const int idx = start + t;
            int c = 0;
            if (idx < HW4) {
                float4 v = base[idx];
                c = (v.x > 0.5f) + (v.y > 0.5f) + (v.z > 0.5f) + (v.w > 0.5f);
            }
            c = __reduce_add_sync(0xffffffffu, c);
            __syncthreads();
            if ((t & 31) == 0) sh[t >> 5] = c;
            __syncthreads();
            if (t == 0) {
                int s = 0;
                #pragma unroll
                for (int i = 0; i < 8; i++) s += sh[i];
                s_val = s;
            }
            __syncthreads();
            total += s_val;
            if (total >= thr) break;          // uniform break
        }
        if (t == 0) g_cnt[b] = total;
    } else if (task == 1) {
        // ---- min_r: top-down row probe ----
        int res = HH;
        for (int r = 0; r < HH; r++) {
            bool hit = false;
            if (t < W4) {
                float4 v = base[(size_t)r * W4 + t];
                hit = (fmaxf(fmaxf(v.x, v.y), fmaxf(v.z, v.w)) > 0.5f);
            }
            if (__syncthreads_or((int)hit)) { res = r; break; }
        }
        if (t == 0) g_minr[b] = res;
    } else if (task == 2) {
        // ---- max_r: bottom-up row probe ----
        int res = -1;
        for (int r = HH - 1; r >= 0; r--) {
            bool hit = false;
            if (t < W4) {
                float4 v = base[(size_t)r * W4 + t];
                hit = (fmaxf(fmaxf(v.x, v.y), fmaxf(v.z, v.w)) > 0.5f);
            }
            if (__syncthreads_or((int)hit)) { res = r; break; }
        }
        if (t == 0) g_maxr[b] = res;
    } else if (task == 3) {
        // ---- min_c: left-to-right float4-column probe ----
        int res = WW;
        for (int cg = 0; cg < W4; cg++) {
            int lm = 1 << 30;
            for (int r = t; r < HH; r += NTA) {
                float4 v = base[(size_t)r * W4 + cg];
                int cm = (v.x > 0.5f) ? 4*cg
                       : (v.y > 0.5f) ? 4*cg + 1
                       : (v.z > 0.5f) ? 4*cg + 2
                       : (v.w > 0.5f) ? 4*cg + 3 : (1 << 30);
                lm = min(lm, cm);
            }
            lm = __reduce_min_sync(0xffffffffu, lm);
            __syncthreads();
            if ((t & 31) == 0) sh[t >> 5] = lm;
            __syncthreads();
            if (t == 0) {
                int s = sh[0];
                #pragma unroll
                for (int i = 1; i < 8; i++) s = min(s, sh[i]);
                s_val = s;
            }
            __syncthreads();
            if (s_val < (1 << 30)) { res = s_val; break; }
        }
        if (t == 0) g_minc[b] = res;
    } else {
        // ---- max_c: right-to-left float4-column probe ----
        int res = -1;
        for (int cg = W4 - 1; cg >= 0; cg--) {
            int lm = -1;
            for (int r = t; r < HH; r += NTA) {
                float4 v = base[(size_t)r * W4 + cg];
                int cm = (v.w > 0.5f) ? 4*cg + 3
                       : (v.z > 0.5f) ? 4*cg + 2
                       : (v.y > 0.5f) ? 4*cg + 1
                       : (v.x > 0.5f) ? 4*cg : -1;
                lm = max(lm, cm);
            }
            lm = __reduce_max_sync(0xffffffffu, lm);
            __syncthreads();
            if ((t & 31) == 0) sh[t >> 5] = lm;
            __syncthreads();
            if (t == 0) {
                int s = sh[0];
                #pragma unroll
                for (int i = 1; i < 8; i++) s = max(s, sh[i]);
                s_val = s;
            }
            __syncthreads();
            if (s_val >= 0) { res = s_val; break; }
        }
        if (t == 0) g_maxc[b] = res;
    }

    // Results are written; let the PDL-dependent fill kernel start.
    cudaTriggerProgrammaticLaunchCompletion();
}

// ---------------------------------------------------------------------------
// Kernel B: fill. Launched with PDL; blocks dispatch while bbox runs and
// synchronize on its completion before reading results.
// ---------------------------------------------------------------------------
__global__ __launch_bounds__(224) void ram_fill(float4* __restrict__ out,
                                                const int* __restrict__ n_pts,
                                                const int* __restrict__ n_loose,
                                                float* __restrict__ out_bbox)
{
    cudaGridDependencySynchronize();   // wait for ram_bbox results

    const int t = threadIdx.x;
    const int b = blockIdx.y;

    __shared__ int4 sbb;
    if (t == 0) {
        const int thr = *n_pts, loose = *n_loose;
        const bool full = g_cnt[b] < thr;
        int y0 = full ? 0      : max(0, min(HH - 1, g_minr[b] - loose));
        int y1 = full ? HH - 1 : max(0, min(HH - 1, g_maxr[b] + loose));
        int x0 = full ? 0      : max(0, min(WW - 1, g_minc[b] - loose));
        int x1 = full ? WW - 1 : max(0, min(WW - 1, g_maxc[b] + loose));
        sbb = make_int4(y0, y1, x0, x1);
        if (out_bbox && blockIdx.x == 0) {
            out_bbox[b * 4 + 0] = (float)y0;
            out_bbox[b * 4 + 1] = (float)y1;
            out_bbox[b * 4 + 2] = (float)x0;
            out_bbox[b * 4 + 3] = (float)x1;
        }
    }
    __syncthreads();
    if (t >= W4) return;

    const int4 bb = sbb;
    const int r0 = blockIdx.x * FROWS;
    const int c = t * 4;
    float4 vin;
    vin.x = (c     >= bb.z && c     <= bb.w) ? 1.f : 0.f;
    vin.y = (c + 1 >= bb.z && c + 1 <= bb.w) ? 1.f : 0.f;
    vin.z = (c + 2 >= bb.z && c + 2 <= bb.w) ? 1.f : 0.f;
    vin.w = (c + 3 >= bb.z && c + 3 <= bb.w) ? 1.f : 0.f;
    const float4 vz = make_float4(0.f, 0.f, 0.f, 0.f);

    float4* p = out + (size_t)b * HW4 + (size_t)r0 * W4 + t;
    #pragma unroll
    for (int j = 0; j < FROWS; j++) {
        const int r = r0 + j;
        p[(size_t)j * W4] = (r >= bb.x && r <= bb.y) ? vin : vz;
    }
}

extern "C" void kernel_launch(void* const* d_in, const int* in_sizes, int n_in,
                              void* d_out, int out_size) {
    const float* mask = (const float*)d_in[0];
    const int* n_pts  = (const int*)d_in[1];
    const int* loose  = (const int*)d_in[2];
    float* out        = (float*)d_out;

    const int B = in_sizes[0] / HWX;
    const int att_elems = B * HWX;
    float* out_bbox = (out_size >= att_elems + 4 * B) ? (out + att_elems) : nullptr;

    ram_bbox<<<dim3(5, B), NTA>>>((const float4*)mask, n_pts);

    // Fill with programmatic dependent launch: overlap its launch/dispatch
    // latency under ram_bbox execution.
    cudaLaunchConfig_t cfg = {};
    cfg.gridDim  = dim3(FBX, B);
    cfg.blockDim = dim3(224, 1, 1);
    cfg.stream   = 0;
    cudaLaunchAttribute attr[1];
    attr[0].id = cudaLaunchAttributeProgrammaticStreamSerialization;
    attr[0].val.programmaticStreamSerializationAllowed = 1;
    cfg.attrs    = attr;
    cfg.numAttrs = 1;
    cudaLaunchKernelEx(&cfg, ram_fill, (float4*)out,
                       (const int*)n_pts, (const int*)loose, out_bbox);
}